// round 13
// baseline (speedup 1.0000x reference)
#include <cuda_runtime.h>
#include <math.h>
#include <stdint.h>

// Problem-fixed sizes: N=100000, E=3200000, NF=16, H=32, HO=64
#define NMAX 100000
#define NF 16
#define H  32
#define HO 64
#define NBANK 8

__device__ float  g_agg[NMAX * NF];
__device__ float  g_h1 [NMAX * H];
__device__ float  g_h2 [NMAX * H];
__device__ double g_s1 [NBANK * 64];   // per-bank: sum[32], sumsq[32]
__device__ double g_s2 [NBANK * 64];
__device__ int    g_is64;

__device__ __forceinline__ float gelu_exact(float v) {
    return 0.5f * v * (1.0f + erff(v * 0.70710678118654752f));
}

// ---------------------------------------------------------------------------
// K0: zero g_agg + banked stats; detect edge_index dtype
// ---------------------------------------------------------------------------
__global__ __launch_bounds__(256) void k_pre(const int* __restrict__ eidx32,
                                             int n4) {
    int i = blockIdx.x * blockDim.x + threadIdx.x;
    if (i < n4) ((float4*)g_agg)[i] = make_float4(0.f, 0.f, 0.f, 0.f);
    if (blockIdx.x == 0) {
        #pragma unroll
        for (int k = 0; k < NBANK * 64 / 256; k++) {
            g_s1[threadIdx.x + k * 256] = 0.0;
            g_s2[threadIdx.x + k * 256] = 0.0;
        }
        if (threadIdx.x == 0) {
            int nz = 0;
            #pragma unroll
            for (int k = 0; k < 64; k++) nz |= eidx32[2 * k + 1];
            g_is64 = (nz == 0) ? 1 : 0;
        }
    }
}

// ---------------------------------------------------------------------------
// K1: edge kernel (R9 config — proven): 4 threads/edge, grid-stride,
// index prefetch, weights in registers, __ldcs streaming for idx/ea.
// ---------------------------------------------------------------------------
__global__ __launch_bounds__(256) void k_edge(const float* __restrict__ x,
                                              const void*  __restrict__ eidx,
                                              const float* __restrict__ ea,
                                              const float* __restrict__ We,
                                              const float* __restrict__ be,
                                              int E) {
    int t = blockIdx.x * blockDim.x + threadIdx.x;
    int c = t & 3;

    float w[8][4];
    #pragma unroll
    for (int k = 0; k < 8; k++) {
        float4 wv = __ldg((const float4*)(We + k * 16) + c);
        w[k][0] = wv.x; w[k][1] = wv.y; w[k][2] = wv.z; w[k][3] = wv.w;
    }
    float4 bv = __ldg(((const float4*)be) + c);
    int is64 = g_is64;

    int total  = E * 4;
    int stride = gridDim.x * blockDim.x;
    const int*       p32 = (const int*)eidx;
    const long long* p64 = (const long long*)eidx;

    int gt = t;
    if (gt >= total) return;

    int src, dst;
    {
        int e = gt >> 2;
        if (is64) { src = (int)__ldcs(p64 + e); dst = (int)__ldcs(p64 + e + E); }
        else      { src = __ldcs(p32 + e);      dst = __ldcs(p32 + e + E);      }
    }

    while (gt < total) {
        int gtn = gt + stride;
        int srcN = 0, dstN = 0;
        if (gtn < total) {
            int en = gtn >> 2;
            if (is64) { srcN = (int)__ldcs(p64 + en); dstN = (int)__ldcs(p64 + en + E); }
            else      { srcN = __ldcs(p32 + en);      dstN = __ldcs(p32 + en + E);      }
        }

        int e = gt >> 2;
        float4 xv = __ldg((const float4*)(x + (size_t)src * 16) + c);
        const float4* ear = (const float4*)(ea + (size_t)e * 8);
        float4 a0 = __ldcs(ear);
        float4 a1 = __ldcs(ear + 1);
        float av[8] = {a0.x, a0.y, a0.z, a0.w, a1.x, a1.y, a1.z, a1.w};

        float m0 = bv.x, m1 = bv.y, m2 = bv.z, m3 = bv.w;
        #pragma unroll
        for (int k = 0; k < 8; k++) {
            m0 = fmaf(av[k], w[k][0], m0);
            m1 = fmaf(av[k], w[k][1], m1);
            m2 = fmaf(av[k], w[k][2], m2);
            m3 = fmaf(av[k], w[k][3], m3);
        }

        float4 r;
        r.x = fmaxf(xv.x + m0, 0.0f);
        r.y = fmaxf(xv.y + m1, 0.0f);
        r.z = fmaxf(xv.z + m2, 0.0f);
        r.w = fmaxf(xv.w + m3, 0.0f);
        atomicAdd((float4*)(g_agg + (size_t)dst * 16) + c, r);

        gt = gtn; src = srcN; dst = dstN;
    }
}

// ---------------------------------------------------------------------------
// stats epilogue (2-thr/node layout): thread lane L holds acc[16] =
// features [(L&1)*16, +16) of node (L>>1). Conflict-free stride-2 reduce.
// ---------------------------------------------------------------------------
__device__ __forceinline__ void stats_epilogue16(const float* acc, bool valid,
                                                 double* sums) {
    __shared__ float tr[8][16][33];
    __shared__ float comb[8][32];
    int lane = threadIdx.x & 31;
    int wid  = threadIdx.x >> 5;
    int f    = lane & 15;
    bool isq = lane >= 16;
    int bank = blockIdx.x & (NBANK - 1);

    #pragma unroll
    for (int j = 0; j < 16; j++)
        tr[wid][j][lane] = valid ? acc[j] : 0.0f;
    __syncwarp();

    float red[2];
    #pragma unroll
    for (int h = 0; h < 2; h++) {
        float r = 0.0f;
        #pragma unroll
        for (int k = 0; k < 16; k++) {
            float v = tr[wid][f][2 * k + h];
            r = fmaf(v, isq ? v : 1.0f, r);
        }
        red[h] = r;
    }

    #pragma unroll
    for (int h = 0; h < 2; h++) {
        comb[wid][lane] = red[h];
        __syncthreads();
        if (wid == 0) {
            float ts = 0.0f;
            #pragma unroll
            for (int w = 0; w < 8; w++) ts += comb[w][lane];
            atomicAdd(&sums[bank * 64 + (isq ? 32 : 0) + h * 16 + f],
                      (double)ts);
        }
        __syncthreads();
    }
}

// ---------------------------------------------------------------------------
// BN finalize inline: sum the 8 banks, then scale/shift
// ---------------------------------------------------------------------------
__device__ __forceinline__ void fin_inline(const double* __restrict__ sums,
                                           const float* __restrict__ gamma,
                                           const float* __restrict__ beta,
                                           int N, float* ssc, float* ssh) {
    if (threadIdx.x < H) {
        int f = threadIdx.x;
        double s = 0.0, q = 0.0;
        #pragma unroll
        for (int b = 0; b < NBANK; b++) {
            s += sums[b * 64 + f];
            q += sums[b * 64 + 32 + f];
        }
        double mean = s / (double)N;
        double var  = q / (double)N - mean * mean;
        double inv  = 1.0 / sqrt(var + 1e-5);
        ssc[f] = (float)((double)gamma[f] * inv);
        ssh[f] = (float)((double)beta[f] - mean * (double)gamma[f] * inv);
    }
}

// ---------------------------------------------------------------------------
// K2: h1 = ((1+eps)*x + agg) @ W1 + b1.  2 thr/node, output split (R12).
// ---------------------------------------------------------------------------
__global__ __launch_bounds__(256) void k_gemm1(const float* __restrict__ x,
                                               const float* __restrict__ epsp,
                                               const float* __restrict__ W1,
                                               const float* __restrict__ b1,
                                               int N) {
    __shared__ float sW[NF * H];
    __shared__ float sb[H];
    for (int i = threadIdx.x; i < NF * H; i += blockDim.x) sW[i] = W1[i];
    if (threadIdx.x < H) sb[threadIdx.x] = b1[threadIdx.x];
    __syncthreads();

    int t = blockIdx.x * blockDim.x + threadIdx.x;
    int n = t >> 1, half = t & 1;
    bool valid = n < N;
    int nc = valid ? n : 0;
    float sc = 1.0f + epsp[0];

    const float4* ar = (const float4*)(g_agg + (size_t)nc * NF);
    const float4* xr = (const float4*)(x     + (size_t)nc * NF);
    int hoff = half * 16;

    float acc[16];
    #pragma unroll
    for (int j = 0; j < 16; j++) acc[j] = sb[hoff + j];

    #pragma unroll 1
    for (int cph = 0; cph < 4; cph++) {
        float4 v  = ar[cph];
        float4 xv = xr[cph];
        float a0 = fmaf(sc, xv.x, v.x);
        float a1 = fmaf(sc, xv.y, v.y);
        float a2 = fmaf(sc, xv.z, v.z);
        float a3 = fmaf(sc, xv.w, v.w);
        const float* w0 = sW + (4 * cph + 0) * H + hoff;
        const float* w1 = sW + (4 * cph + 1) * H + hoff;
        const float* w2 = sW + (4 * cph + 2) * H + hoff;
        const float* w3 = sW + (4 * cph + 3) * H + hoff;
        #pragma unroll
        for (int j = 0; j < 16; j++) {
            float t0 = fmaf(a0, w0[j], acc[j]);
            float t1 = fmaf(a1, w1[j], t0);
            float t2 = fmaf(a2, w2[j], t1);
            acc[j]   = fmaf(a3, w3[j], t2);
        }
    }

    if (valid) {
        float4* hr = (float4*)(g_h1 + (size_t)n * H + hoff);
        #pragma unroll
        for (int cph = 0; cph < 4; cph++)
            hr[cph] = make_float4(acc[4*cph], acc[4*cph+1], acc[4*cph+2], acc[4*cph+3]);
    }
    stats_epilogue16(acc, valid, g_s1);
}

// ---------------------------------------------------------------------------
// K3: h2 = gelu(bn1(h1)) @ W2 + b2.  2 thr/node, INPUT SPLIT: each half
// computes 16 gelu (its input chunk), partial sums for all 32 outputs,
// 16-shuffle combine with the pair lane. No duplicated gelu or reads.
// ---------------------------------------------------------------------------
__global__ __launch_bounds__(256) void k_gemm2(const float* __restrict__ g1,
                                               const float* __restrict__ bt1,
                                               const float* __restrict__ W2,
                                               const float* __restrict__ b2,
                                               int N) {
    __shared__ float sW[H * H];
    __shared__ float sb[H], ssc[H], ssh[H];
    for (int i = threadIdx.x; i < H * H; i += blockDim.x) sW[i] = W2[i];
    if (threadIdx.x < H) sb[threadIdx.x] = b2[threadIdx.x];
    fin_inline(g_s1, g1, bt1, N, ssc, ssh);
    __syncthreads();

    int t = blockIdx.x * blockDim.x + threadIdx.x;
    int n = t >> 1, half = t & 1;
    bool valid = n < N;
    int nc = valid ? n : 0;
    int koff = half * 16;                 // this thread's input-feature chunk
    int hoff = half * 16;                 // this thread's output half
    int poff = 16 - hoff;                 // partner's output half

    // 16 gelu inputs (own chunk only)
    const float4* hr = (const float4*)(g_h1 + (size_t)nc * H + koff);
    float y[16];
    #pragma unroll
    for (int cph = 0; cph < 4; cph++) {
        float4 v = hr[cph];
        y[4*cph+0] = gelu_exact(fmaf(v.x, ssc[koff+4*cph+0], ssh[koff+4*cph+0]));
        y[4*cph+1] = gelu_exact(fmaf(v.y, ssc[koff+4*cph+1], ssh[koff+4*cph+1]));
        y[4*cph+2] = gelu_exact(fmaf(v.z, ssc[koff+4*cph+2], ssh[koff+4*cph+2]));
        y[4*cph+3] = gelu_exact(fmaf(v.w, ssc[koff+4*cph+3], ssh[koff+4*cph+3]));
    }

    // partials: po = my-output-half, pp = partner-output-half.
    // Even lane carries the biases (added exactly once per output).
    float po[16], pp[16];
    #pragma unroll
    for (int j = 0; j < 16; j++) {
        po[j] = (half == 0) ? sb[j]      : 0.0f;
        pp[j] = (half == 0) ? sb[16 + j] : 0.0f;
    }
    #pragma unroll 4
    for (int k = 0; k < 16; k++) {
        const float* wr = sW + (koff + k) * H;
        float yk = y[k];
        #pragma unroll
        for (int j = 0; j < 16; j++) {
            po[j] = fmaf(yk, wr[hoff + j], po[j]);
            pp[j] = fmaf(yk, wr[poff + j], pp[j]);
        }
    }

    // combine: my outputs = po + partner's pp (partner's partner == me)
    float tot[16];
    #pragma unroll
    for (int j = 0; j < 16; j++)
        tot[j] = po[j] + __shfl_xor_sync(0xffffffffu, pp[j], 1);

    if (valid) {
        float4* o = (float4*)(g_h2 + (size_t)n * H + hoff);
        #pragma unroll
        for (int cph = 0; cph < 4; cph++)
            o[cph] = make_float4(tot[4*cph], tot[4*cph+1], tot[4*cph+2], tot[4*cph+3]);
    }
    stats_epilogue16(tot, valid, g_s2);
}

// ---------------------------------------------------------------------------
// K4: out = gelu(bn2(h2)) @ W3 + b3.  2 thr/node, output split, gelu SHARED:
// each thread computes 16 gelu (own input chunk) + 16 shuffles for the rest.
// ---------------------------------------------------------------------------
__global__ __launch_bounds__(256) void k_out(const float* __restrict__ g2,
                                             const float* __restrict__ bt2,
                                             const float* __restrict__ W3,
                                             const float* __restrict__ b3,
                                             float* __restrict__ out,
                                             int N) {
    __shared__ float sW[H * HO];
    __shared__ float sb[HO], ssc[H], ssh[H];
    for (int i = threadIdx.x; i < H * HO; i += blockDim.x) sW[i] = W3[i];
    if (threadIdx.x < HO) sb[threadIdx.x] = b3[threadIdx.x];
    fin_inline(g_s2, g2, bt2, N, ssc, ssh);
    __syncthreads();

    int t = blockIdx.x * blockDim.x + threadIdx.x;
    int n = t >> 1, half = t & 1;
    bool valid = n < N;
    int nc = valid ? n : 0;
    int koff = half * 16;

    // own 16 gelu
    const float4* hr = (const float4*)(g_h2 + (size_t)nc * H + koff);
    float yo[16];
    #pragma unroll
    for (int cph = 0; cph < 4; cph++) {
        float4 v = hr[cph];
        yo[4*cph+0] = gelu_exact(fmaf(v.x, ssc[koff+4*cph+0], ssh[koff+4*cph+0]));
        yo[4*cph+1] = gelu_exact(fmaf(v.y, ssc[koff+4*cph+1], ssh[koff+4*cph+1]));
        yo[4*cph+2] = gelu_exact(fmaf(v.z, ssc[koff+4*cph+2], ssh[koff+4*cph+2]));
        yo[4*cph+3] = gelu_exact(fmaf(v.w, ssc[koff+4*cph+3], ssh[koff+4*cph+3]));
    }
    // partner's 16 via shuffle
    float yp[16];
    #pragma unroll
    for (int i = 0; i < 16; i++)
        yp[i] = __shfl_xor_sync(0xffffffffu, yo[i], 1);

    if (!valid) return;
    int ooffb = half * 32;                // this thread's 32 outputs
    float4* orow = (float4*)(out + (size_t)n * HO + ooffb);

    #pragma unroll 1
    for (int p = 0; p < 2; p++) {
        int ooff = ooffb + p * 16;
        float acc[16];
        #pragma unroll
        for (int j = 0; j < 16; j++) acc[j] = sb[ooff + j];
        #pragma unroll 4
        for (int k = 0; k < 32; k++) {
            // feature k: own chunk is [koff, koff+16)
            float yk = (half == 0) ? ((k < 16) ? yo[k & 15] : yp[k & 15])
                                   : ((k < 16) ? yp[k & 15] : yo[k & 15]);
            const float* wr = sW + k * HO;
            #pragma unroll
            for (int j = 0; j < 16; j++) acc[j] = fmaf(yk, wr[ooff + j], acc[j]);
        }
        #pragma unroll
        for (int cph = 0; cph < 4; cph++)
            orow[p * 4 + cph] = make_float4(acc[4*cph], acc[4*cph+1],
                                            acc[4*cph+2], acc[4*cph+3]);
    }
}

// ---------------------------------------------------------------------------
extern "C" void kernel_launch(void* const* d_in, const int* in_sizes, int n_in,
                              void* d_out, int out_size) {
    const float* x    = (const float*)d_in[0];
    const void*  eidx =               d_in[1];
    const float* ea   = (const float*)d_in[2];
    const float* We   = (const float*)d_in[3];
    const float* be   = (const float*)d_in[4];
    const float* W1   = (const float*)d_in[5];
    const float* b1   = (const float*)d_in[6];
    const float* g1   = (const float*)d_in[7];
    const float* bt1  = (const float*)d_in[8];
    const float* W2   = (const float*)d_in[9];
    const float* b2   = (const float*)d_in[10];
    const float* epsp = (const float*)d_in[11];
    const float* g2   = (const float*)d_in[12];
    const float* bt2  = (const float*)d_in[13];
    const float* W3   = (const float*)d_in[14];
    const float* b3   = (const float*)d_in[15];
    float* out = (float*)d_out;

    int N = in_sizes[0] / NF;
    int E = in_sizes[2] / 8;
    int n4 = N * NF / 4;
    int nb2 = (2 * N + 255) / 256;   // 2 threads per node

    k_pre  <<<(n4 + 255) / 256, 256>>>((const int*)eidx, n4);
    k_edge <<<2048, 256>>>(x, eidx, ea, We, be, E);
    k_gemm1<<<nb2, 256>>>(x, epsp, W1, b1, N);
    k_gemm2<<<nb2, 256>>>(g1, bt1, W2, b2, N);       // profiled (launch idx 3)
    k_out  <<<nb2, 256>>>(g2, bt2, W3, b3, out, N);
}

// round 14
// speedup vs baseline: 1.1837x; 1.1837x over previous
#include <cuda_runtime.h>
#include <math.h>
#include <stdint.h>

// Problem-fixed sizes: N=100000, E=3200000, NF=16, H=32, HO=64
#define NMAX 100000
#define NF 16
#define H  32
#define HO 64
#define NBANK 8

__device__ float  g_agg[NMAX * NF];
__device__ float  g_h1 [NMAX * H];
__device__ float  g_h2 [NMAX * H];
__device__ double g_s1 [NBANK * 64];   // per-bank: sum[32], sumsq[32]
__device__ double g_s2 [NBANK * 64];
__device__ int    g_is64;

__device__ __forceinline__ float gelu_exact(float v) {
    return 0.5f * v * (1.0f + erff(v * 0.70710678118654752f));
}

// ---------------------------------------------------------------------------
// K0: zero g_agg + banked stats; detect edge_index dtype
// ---------------------------------------------------------------------------
__global__ __launch_bounds__(256) void k_pre(const int* __restrict__ eidx32,
                                             int n4) {
    int i = blockIdx.x * blockDim.x + threadIdx.x;
    if (i < n4) ((float4*)g_agg)[i] = make_float4(0.f, 0.f, 0.f, 0.f);
    if (blockIdx.x == 0) {
        #pragma unroll
        for (int k = 0; k < NBANK * 64 / 256; k++) {
            g_s1[threadIdx.x + k * 256] = 0.0;
            g_s2[threadIdx.x + k * 256] = 0.0;
        }
        if (threadIdx.x == 0) {
            int nz = 0;
            #pragma unroll
            for (int k = 0; k < 64; k++) nz |= eidx32[2 * k + 1];
            g_is64 = (nz == 0) ? 1 : 0;
        }
    }
}

// ---------------------------------------------------------------------------
// K1: edge kernel (R9 — proven 82.7us): 4 threads/edge, grid-stride,
// index prefetch, weights in registers, __ldcs streaming for idx/ea.
// ---------------------------------------------------------------------------
__global__ __launch_bounds__(256) void k_edge(const float* __restrict__ x,
                                              const void*  __restrict__ eidx,
                                              const float* __restrict__ ea,
                                              const float* __restrict__ We,
                                              const float* __restrict__ be,
                                              int E) {
    int t = blockIdx.x * blockDim.x + threadIdx.x;
    int c = t & 3;

    float w[8][4];
    #pragma unroll
    for (int k = 0; k < 8; k++) {
        float4 wv = __ldg((const float4*)(We + k * 16) + c);
        w[k][0] = wv.x; w[k][1] = wv.y; w[k][2] = wv.z; w[k][3] = wv.w;
    }
    float4 bv = __ldg(((const float4*)be) + c);
    int is64 = g_is64;

    int total  = E * 4;
    int stride = gridDim.x * blockDim.x;
    const int*       p32 = (const int*)eidx;
    const long long* p64 = (const long long*)eidx;

    int gt = t;
    if (gt >= total) return;

    int src, dst;
    {
        int e = gt >> 2;
        if (is64) { src = (int)__ldcs(p64 + e); dst = (int)__ldcs(p64 + e + E); }
        else      { src = __ldcs(p32 + e);      dst = __ldcs(p32 + e + E);      }
    }

    while (gt < total) {
        int gtn = gt + stride;
        int srcN = 0, dstN = 0;
        if (gtn < total) {
            int en = gtn >> 2;
            if (is64) { srcN = (int)__ldcs(p64 + en); dstN = (int)__ldcs(p64 + en + E); }
            else      { srcN = __ldcs(p32 + en);      dstN = __ldcs(p32 + en + E);      }
        }

        int e = gt >> 2;
        float4 xv = __ldg((const float4*)(x + (size_t)src * 16) + c);
        const float4* ear = (const float4*)(ea + (size_t)e * 8);
        float4 a0 = __ldcs(ear);
        float4 a1 = __ldcs(ear + 1);
        float av[8] = {a0.x, a0.y, a0.z, a0.w, a1.x, a1.y, a1.z, a1.w};

        float m0 = bv.x, m1 = bv.y, m2 = bv.z, m3 = bv.w;
        #pragma unroll
        for (int k = 0; k < 8; k++) {
            m0 = fmaf(av[k], w[k][0], m0);
            m1 = fmaf(av[k], w[k][1], m1);
            m2 = fmaf(av[k], w[k][2], m2);
            m3 = fmaf(av[k], w[k][3], m3);
        }

        float4 r;
        r.x = fmaxf(xv.x + m0, 0.0f);
        r.y = fmaxf(xv.y + m1, 0.0f);
        r.z = fmaxf(xv.z + m2, 0.0f);
        r.w = fmaxf(xv.w + m3, 0.0f);
        atomicAdd((float4*)(g_agg + (size_t)dst * 16) + c, r);

        gt = gtn; src = srcN; dst = dstN;
    }
}

// ---------------------------------------------------------------------------
// stats epilogue, acc[32] per thread (1 thr/node kernels)
// ---------------------------------------------------------------------------
__device__ __forceinline__ void stats_epilogue(const float* acc, bool valid,
                                               double* sums) {
    __shared__ float tr[8][16][33];
    __shared__ float comb[8][32];
    int lane = threadIdx.x & 31;
    int wid  = threadIdx.x >> 5;
    int f    = lane & 15;
    bool isq = lane >= 16;
    int bank = blockIdx.x & (NBANK - 1);

    float red[2];
    #pragma unroll
    for (int half = 0; half < 2; half++) {
        if (half) __syncwarp();
        #pragma unroll
        for (int j = 0; j < 16; j++)
            tr[wid][j][lane] = valid ? acc[half * 16 + j] : 0.0f;
        __syncwarp();
        float r = 0.0f;
        #pragma unroll
        for (int k = 0; k < 32; k++) {
            float v = tr[wid][f][k];
            r = fmaf(v, isq ? v : 1.0f, r);
        }
        red[half] = r;
    }

    #pragma unroll
    for (int half = 0; half < 2; half++) {
        comb[wid][lane] = red[half];
        __syncthreads();
        if (wid == 0) {
            float ts = 0.0f;
            #pragma unroll
            for (int w = 0; w < 8; w++) ts += comb[w][lane];
            atomicAdd(&sums[bank * 64 + (isq ? 32 : 0) + half * 16 + f],
                      (double)ts);
        }
        __syncthreads();
    }
}

// ---------------------------------------------------------------------------
// stats epilogue, acc[16] per thread (2 thr/node layout, gemm1 only):
// lane L holds features [(L&1)*16,+16) of node (L>>1); stride-2 reduce.
// ---------------------------------------------------------------------------
__device__ __forceinline__ void stats_epilogue16(const float* acc, bool valid,
                                                 double* sums) {
    __shared__ float tr[8][16][33];
    __shared__ float comb[8][32];
    int lane = threadIdx.x & 31;
    int wid  = threadIdx.x >> 5;
    int f    = lane & 15;
    bool isq = lane >= 16;
    int bank = blockIdx.x & (NBANK - 1);

    #pragma unroll
    for (int j = 0; j < 16; j++)
        tr[wid][j][lane] = valid ? acc[j] : 0.0f;
    __syncwarp();

    float red[2];
    #pragma unroll
    for (int h = 0; h < 2; h++) {
        float r = 0.0f;
        #pragma unroll
        for (int k = 0; k < 16; k++) {
            float v = tr[wid][f][2 * k + h];
            r = fmaf(v, isq ? v : 1.0f, r);
        }
        red[h] = r;
    }

    #pragma unroll
    for (int h = 0; h < 2; h++) {
        comb[wid][lane] = red[h];
        __syncthreads();
        if (wid == 0) {
            float ts = 0.0f;
            #pragma unroll
            for (int w = 0; w < 8; w++) ts += comb[w][lane];
            atomicAdd(&sums[bank * 64 + (isq ? 32 : 0) + h * 16 + f],
                      (double)ts);
        }
        __syncthreads();
    }
}

// ---------------------------------------------------------------------------
// BN finalize inline: sum the 8 banks, then scale/shift
// ---------------------------------------------------------------------------
__device__ __forceinline__ void fin_inline(const double* __restrict__ sums,
                                           const float* __restrict__ gamma,
                                           const float* __restrict__ beta,
                                           int N, float* ssc, float* ssh) {
    if (threadIdx.x < H) {
        int f = threadIdx.x;
        double s = 0.0, q = 0.0;
        #pragma unroll
        for (int b = 0; b < NBANK; b++) {
            s += sums[b * 64 + f];
            q += sums[b * 64 + 32 + f];
        }
        double mean = s / (double)N;
        double var  = q / (double)N - mean * mean;
        double inv  = 1.0 / sqrt(var + 1e-5);
        ssc[f] = (float)((double)gamma[f] * inv);
        ssh[f] = (float)((double)beta[f] - mean * (double)gamma[f] * inv);
    }
}

// ---------------------------------------------------------------------------
// K2: h1 = ((1+eps)*x + agg) @ W1 + b1.  R12 form (proven 14.7us):
// 2 threads/node, output split, acc[16], no gelu so no duplication.
// ---------------------------------------------------------------------------
__global__ __launch_bounds__(256) void k_gemm1(const float* __restrict__ x,
                                               const float* __restrict__ epsp,
                                               const float* __restrict__ W1,
                                               const float* __restrict__ b1,
                                               int N) {
    __shared__ float sW[NF * H];
    __shared__ float sb[H];
    for (int i = threadIdx.x; i < NF * H; i += blockDim.x) sW[i] = W1[i];
    if (threadIdx.x < H) sb[threadIdx.x] = b1[threadIdx.x];
    __syncthreads();

    int t = blockIdx.x * blockDim.x + threadIdx.x;
    int n = t >> 1, half = t & 1;
    bool valid = n < N;
    int nc = valid ? n : 0;
    float sc = 1.0f + epsp[0];

    const float4* ar = (const float4*)(g_agg + (size_t)nc * NF);
    const float4* xr = (const float4*)(x     + (size_t)nc * NF);
    int hoff = half * 16;

    float acc[16];
    #pragma unroll
    for (int j = 0; j < 16; j++) acc[j] = sb[hoff + j];

    #pragma unroll 1
    for (int cph = 0; cph < 4; cph++) {
        float4 v  = ar[cph];
        float4 xv = xr[cph];
        float a0 = fmaf(sc, xv.x, v.x);
        float a1 = fmaf(sc, xv.y, v.y);
        float a2 = fmaf(sc, xv.z, v.z);
        float a3 = fmaf(sc, xv.w, v.w);
        const float* w0 = sW + (4 * cph + 0) * H + hoff;
        const float* w1 = sW + (4 * cph + 1) * H + hoff;
        const float* w2 = sW + (4 * cph + 2) * H + hoff;
        const float* w3 = sW + (4 * cph + 3) * H + hoff;
        #pragma unroll
        for (int j = 0; j < 16; j++) {
            float t0 = fmaf(a0, w0[j], acc[j]);
            float t1 = fmaf(a1, w1[j], t0);
            float t2 = fmaf(a2, w2[j], t1);
            acc[j]   = fmaf(a3, w3[j], t2);
        }
    }

    if (valid) {
        float4* hr = (float4*)(g_h1 + (size_t)n * H + hoff);
        #pragma unroll
        for (int cph = 0; cph < 4; cph++)
            hr[cph] = make_float4(acc[4*cph], acc[4*cph+1], acc[4*cph+2], acc[4*cph+3]);
    }
    stats_epilogue16(acc, valid, g_s1);
}

// ---------------------------------------------------------------------------
// K3: h2 = gelu(bn1(h1)) @ W2 + b2.  R9 form: 1 thr/node, streamed inputs.
// ---------------------------------------------------------------------------
__global__ __launch_bounds__(256) void k_gemm2(const float* __restrict__ g1,
                                               const float* __restrict__ bt1,
                                               const float* __restrict__ W2,
                                               const float* __restrict__ b2,
                                               int N) {
    __shared__ float sW[H * H];
    __shared__ float sb[H], ssc[H], ssh[H];
    for (int i = threadIdx.x; i < H * H; i += blockDim.x) sW[i] = W2[i];
    if (threadIdx.x < H) sb[threadIdx.x] = b2[threadIdx.x];
    fin_inline(g_s1, g1, bt1, N, ssc, ssh);
    __syncthreads();

    int n = blockIdx.x * blockDim.x + threadIdx.x;
    bool valid = n < N;
    int nc = valid ? n : 0;
    const float4* hr = (const float4*)(g_h1 + (size_t)nc * H);

    float acc[H];
    #pragma unroll
    for (int j = 0; j < H; j++) acc[j] = sb[j];

    #pragma unroll 1
    for (int cph = 0; cph < 8; cph++) {
        float4 v = hr[cph];
        float y0 = gelu_exact(fmaf(v.x, ssc[4*cph+0], ssh[4*cph+0]));
        float y1 = gelu_exact(fmaf(v.y, ssc[4*cph+1], ssh[4*cph+1]));
        float y2 = gelu_exact(fmaf(v.z, ssc[4*cph+2], ssh[4*cph+2]));
        float y3 = gelu_exact(fmaf(v.w, ssc[4*cph+3], ssh[4*cph+3]));
        const float* w0 = sW + (4 * cph + 0) * H;
        const float* w1 = sW + (4 * cph + 1) * H;
        const float* w2 = sW + (4 * cph + 2) * H;
        const float* w3 = sW + (4 * cph + 3) * H;
        #pragma unroll
        for (int j = 0; j < H; j++) {
            float t0 = fmaf(y0, w0[j], acc[j]);
            float t1 = fmaf(y1, w1[j], t0);
            float t2 = fmaf(y2, w2[j], t1);
            acc[j]   = fmaf(y3, w3[j], t2);
        }
    }

    if (valid) {
        float4* o = (float4*)(g_h2 + (size_t)n * H);
        #pragma unroll
        for (int cph = 0; cph < H / 4; cph++)
            o[cph] = make_float4(acc[4*cph], acc[4*cph+1], acc[4*cph+2], acc[4*cph+3]);
    }
    stats_epilogue(acc, valid, g_s2);
}

// ---------------------------------------------------------------------------
// K4: out = gelu(bn2(h2)) @ W3 + b3.  R9 form: y[32] once, 2 passes acc[32].
// ---------------------------------------------------------------------------
__global__ __launch_bounds__(256) void k_out(const float* __restrict__ g2,
                                             const float* __restrict__ bt2,
                                             const float* __restrict__ W3,
                                             const float* __restrict__ b3,
                                             float* __restrict__ out,
                                             int N) {
    __shared__ float sW[H * HO];
    __shared__ float sb[HO], ssc[H], ssh[H];
    for (int i = threadIdx.x; i < H * HO; i += blockDim.x) sW[i] = W3[i];
    if (threadIdx.x < HO) sb[threadIdx.x] = b3[threadIdx.x];
    fin_inline(g_s2, g2, bt2, N, ssc, ssh);
    __syncthreads();

    int n = blockIdx.x * blockDim.x + threadIdx.x;
    if (n >= N) return;
    const float4* hr = (const float4*)(g_h2 + (size_t)n * H);
    float4* orow = (float4*)(out + (size_t)n * HO);

    float y[H];
    #pragma unroll
    for (int cph = 0; cph < 8; cph++) {
        float4 v = hr[cph];
        y[4*cph+0] = gelu_exact(fmaf(v.x, ssc[4*cph+0], ssh[4*cph+0]));
        y[4*cph+1] = gelu_exact(fmaf(v.y, ssc[4*cph+1], ssh[4*cph+1]));
        y[4*cph+2] = gelu_exact(fmaf(v.z, ssc[4*cph+2], ssh[4*cph+2]));
        y[4*cph+3] = gelu_exact(fmaf(v.w, ssc[4*cph+3], ssh[4*cph+3]));
    }

    #pragma unroll 1
    for (int jb = 0; jb < 2; jb++) {
        float acc[32];
        #pragma unroll
        for (int j = 0; j < 32; j++) acc[j] = sb[jb * 32 + j];
        #pragma unroll
        for (int k = 0; k < H; k++) {
            const float* wr = sW + k * HO + jb * 32;
            #pragma unroll
            for (int j = 0; j < 32; j++) acc[j] = fmaf(y[k], wr[j], acc[j]);
        }
        #pragma unroll
        for (int cph = 0; cph < 8; cph++)
            orow[jb * 8 + cph] = make_float4(acc[4*cph], acc[4*cph+1],
                                             acc[4*cph+2], acc[4*cph+3]);
    }
}

// ---------------------------------------------------------------------------
extern "C" void kernel_launch(void* const* d_in, const int* in_sizes, int n_in,
                              void* d_out, int out_size) {
    const float* x    = (const float*)d_in[0];
    const void*  eidx =               d_in[1];
    const float* ea   = (const float*)d_in[2];
    const float* We   = (const float*)d_in[3];
    const float* be   = (const float*)d_in[4];
    const float* W1   = (const float*)d_in[5];
    const float* b1   = (const float*)d_in[6];
    const float* g1   = (const float*)d_in[7];
    const float* bt1  = (const float*)d_in[8];
    const float* W2   = (const float*)d_in[9];
    const float* b2   = (const float*)d_in[10];
    const float* epsp = (const float*)d_in[11];
    const float* g2   = (const float*)d_in[12];
    const float* bt2  = (const float*)d_in[13];
    const float* W3   = (const float*)d_in[14];
    const float* b3   = (const float*)d_in[15];
    float* out = (float*)d_out;

    int N = in_sizes[0] / NF;
    int E = in_sizes[2] / 8;
    int n4 = N * NF / 4;
    int nb  = (N + 255) / 256;       // 1 thread per node
    int nb2 = (2 * N + 255) / 256;   // 2 threads per node (gemm1)

    k_pre  <<<(n4 + 255) / 256, 256>>>((const int*)eidx, n4);
    k_edge <<<2048, 256>>>(x, eidx, ea, We, be, E);
    k_gemm1<<<nb2, 256>>>(x, epsp, W1, b1, N);
    k_gemm2<<<nb,  256>>>(g1, bt1, W2, b2, N);       // profiled (launch idx 3)
    k_out  <<<nb,  256>>>(g2, bt2, W3, b3, out, N);
}